// round 5
// baseline (speedup 1.0000x reference)
#include <cuda_runtime.h>
#include <cuda_bf16.h>
#include <cstdint>

#define BATCH   16
#define NPRED   25200
#define NC      80
#define STRIDE  85
#define TOPK    4096
#define MAXDET  1000
#define NWORDS  64            // TOPK/64
#define NITEMS  25            // ceil(NPRED/1024)
#define CONF_THRES 0.25f
#define IOU_THRES  0.45f
#define MAX_WH     7680.0f

typedef unsigned long long ull;

// ---------------- scratch (no allocation allowed; __device__ globals) ----------------
__device__ unsigned  g_u[BATCH * NPRED];        // order key (score part)
__device__ float     g_s[BATCH * NPRED];        // s = valid ? conf : -1
__device__ int       g_cls[BATCH * NPRED];      // argmax class
__device__ float     g_selScore[BATCH * TOPK];
__device__ int       g_selCls[BATCH * TOPK];
__device__ unsigned  g_clsPack[BATCH * TOPK / 4]; // classes as packed bytes
__device__ float     g_box[BATCH * TOPK * 4];   // xyxy (no offset)
__device__ float     g_ob[BATCH * TOPK * 4];    // offset boxes
__device__ float     g_area[BATCH * TOPK];      // area of offset box
__device__ ull       g_mask[(size_t)BATCH * TOPK * NWORDS]; // sparse: only flagged words valid
__device__ ull       g_rowNZ[BATCH * TOPK];     // per-row bitmap of nonzero mask words
__device__ int       g_nvalid[BATCH];

// ---------------- kernel 1: conf / argmax / order-key, one warp per row --------------
__global__ void k_prep(const float* __restrict__ pred) {
    int gw   = (blockIdx.x * blockDim.x + threadIdx.x) >> 5;  // global warp = row
    int lane = threadIdx.x & 31;
    if (gw >= BATCH * NPRED) return;
    const float* p = pred + (size_t)gw * STRIDE;
    float obj = p[4];
    float best = -1.0f; int bi = 0;
    #pragma unroll
    for (int c = lane; c < NC; c += 32) {
        float v = __fmul_rn(obj, p[5 + c]);
        if (v > best) { best = v; bi = c; }          // strict > keeps first max
    }
    #pragma unroll
    for (int o = 16; o; o >>= 1) {
        float b2 = __shfl_xor_sync(0xFFFFFFFFu, best, o);
        int   i2 = __shfl_xor_sync(0xFFFFFFFFu, bi, o);
        if (b2 > best || (b2 == best && i2 < bi)) { best = b2; bi = i2; }
    }
    if (lane == 0) {
        float s = (best > CONF_THRES) ? best : -1.0f;
        unsigned ub = __float_as_uint(s);
        unsigned uo = (ub & 0x80000000u) ? ~ub : (ub | 0x80000000u); // ascending order map
        g_s[gw] = s; g_u[gw] = uo; g_cls[gw] = bi;
    }
}

// ---------------- kernel 2: top-4096 (reg keys + 2-bit search) + hybrid bitonic ------
__device__ __forceinline__ ull shfl_xor_u64(ull x, int m) {
    unsigned lo = __shfl_xor_sync(0xFFFFFFFFu, (unsigned)x, m);
    unsigned hi = __shfl_xor_sync(0xFFFFFFFFu, (unsigned)(x >> 32), m);
    return ((ull)hi << 32) | lo;
}

__global__ void __launch_bounds__(1024) k_select(const float* __restrict__ pred) {
    int b = blockIdx.x;
    int tid = threadIdx.x;
    int lane = tid & 31;
    const unsigned* u = g_u + b * NPRED;
    __shared__ ull keys[TOPK];
    __shared__ ull sT;
    __shared__ int sCnt0, sCnt1, sCnt2;
    __shared__ int scnt, svalid;

    // zero the rowNZ bitmap for this batch (read by k_suppress, set by k_mask)
    #pragma unroll
    for (int t4 = tid; t4 < TOPK; t4 += 1024) g_rowNZ[b * TOPK + t4] = 0ULL;

    // ---- load all keys into registers (full MLP, one pass over memory) ----
    unsigned uv[NITEMS];
    #pragma unroll
    for (int k = 0; k < NITEMS; ++k) {
        int i = k * 1024 + tid;
        uv[k] = (i < NPRED) ? u[i] : 0u;
    }
    if (tid == 0) { sT = 0ULL; sCnt0 = 0; sCnt1 = 0; sCnt2 = 0; scnt = 0; svalid = 0; }
    __syncthreads();

    // ---- 2-bit-per-step binary search for T = TOPK-th largest key ((u<<32)|~i) ----
    for (int s = 62; s >= 0; s -= 2) {
        ull T = sT;
        ull c1t = T + (1ULL << s);
        int c1 = 0, c2 = 0, c3 = 0;
        #pragma unroll
        for (int k = 0; k < NITEMS; ++k) {
            int i = k * 1024 + tid;
            if (i < NPRED) {
                ull key = ((ull)uv[k] << 32) | (unsigned)(~i);
                if (key >= c1t) {
                    ull w = (key - T) >> s;
                    c1++;
                    if (w >= 2) c2++;
                    if (w >= 3) c3++;
                }
            }
        }
        c1 = __reduce_add_sync(0xFFFFFFFFu, c1);
        c2 = __reduce_add_sync(0xFFFFFFFFu, c2);
        c3 = __reduce_add_sync(0xFFFFFFFFu, c3);
        if (lane == 0) {
            atomicAdd(&sCnt0, c1);
            atomicAdd(&sCnt1, c2);
            atomicAdd(&sCnt2, c3);
        }
        __syncthreads();
        if (tid == 0) {
            int v = (sCnt2 >= TOPK) ? 3 : (sCnt1 >= TOPK) ? 2 : (sCnt0 >= TOPK) ? 1 : 0;
            sT = T | ((ull)v << s);
            sCnt0 = 0; sCnt1 = 0; sCnt2 = 0;
        }
        __syncthreads();
    }
    ull T = sT;

    // ---- gather exactly-4096 keys >= T (warp-aggregated positions) ----
    #pragma unroll
    for (int k = 0; k < NITEMS; ++k) {
        int i = k * 1024 + tid;
        bool m = (i < NPRED);
        ull key = 0ULL;
        if (m) { key = ((ull)uv[k] << 32) | (unsigned)(~i); m = (key >= T); }
        unsigned act = __ballot_sync(0xFFFFFFFFu, m);
        if (m) {
            int leader = __ffs(act) - 1;
            int rank = __popc(act & ((1u << lane) - 1u));
            int base;
            if (lane == leader) base = atomicAdd(&scnt, __popc(act));
            base = __shfl_sync(act, base, leader);
            int pos = base + rank;
            if (pos < TOPK) keys[pos] = key;
        }
    }
    __syncthreads();

    // ---- hybrid bitonic sort, descending: 4 elems/thread (blocked) ----
    ull v[4];
    #pragma unroll
    for (int e = 0; e < 4; ++e) v[e] = keys[tid * 4 + e];

    for (int k = 2; k <= TOPK; k <<= 1) {
        for (int j = k >> 1; j >= 1; j >>= 1) {
            if (j >= 128) {
                #pragma unroll
                for (int e = 0; e < 4; ++e) keys[tid * 4 + e] = v[e];
                __syncthreads();
                #pragma unroll
                for (int e = 0; e < 4; ++e) {
                    int idx = tid * 4 + e;
                    ull pv = keys[idx ^ j];
                    bool d = ((idx & k) == 0);
                    bool lower = ((idx & j) == 0);
                    bool keepmax = (d == lower);
                    ull mx = (v[e] > pv) ? v[e] : pv;
                    ull mn = (v[e] > pv) ? pv : v[e];
                    v[e] = keepmax ? mx : mn;
                }
                __syncthreads();
            } else if (j >= 4) {
                int dl = j >> 2;
                #pragma unroll
                for (int e = 0; e < 4; ++e) {
                    ull pv = shfl_xor_u64(v[e], dl);
                    int idx = tid * 4 + e;
                    bool d = ((idx & k) == 0);
                    bool lower = ((tid & dl) == 0);
                    bool keepmax = (d == lower);
                    ull mx = (v[e] > pv) ? v[e] : pv;
                    ull mn = (v[e] > pv) ? pv : v[e];
                    v[e] = keepmax ? mx : mn;
                }
            } else {
                #pragma unroll
                for (int e = 0; e < 4; ++e) {
                    if ((e & j) == 0) {
                        int idx = tid * 4 + e;
                        bool d = ((idx & k) == 0);
                        ull a = v[e], c2 = v[e + j];
                        if (d ? (a < c2) : (a > c2)) { v[e] = c2; v[e + j] = a; }
                    }
                }
            }
        }
    }

    // ---- emit + fused gather of boxes / classes / areas ----
    int lv = 0;
    #pragma unroll
    for (int e = 0; e < 4; ++e) {
        int rank = tid * 4 + e;
        ull key = v[e];
        int i = (int)(~(unsigned)(key & 0xFFFFFFFFull));
        int gi = b * TOPK + rank;
        float s = g_s[b * NPRED + i];
        g_selScore[gi] = s;
        lv += (s > 0.0f);
        int ci = g_cls[b * NPRED + i];
        g_selCls[gi] = ci;
        ((unsigned char*)g_clsPack)[gi] = (unsigned char)ci;
        const float* p = pred + ((size_t)b * NPRED + i) * STRIDE;
        float xc = p[0], yc = p[1], w = p[2], h = p[3];
        float hw = __fmul_rn(w, 0.5f), hh = __fmul_rn(h, 0.5f);
        float x1 = __fsub_rn(xc, hw), y1 = __fsub_rn(yc, hh);
        float x2 = __fadd_rn(xc, hw), y2 = __fadd_rn(yc, hh);
        float off = __fmul_rn((float)ci, MAX_WH);
        float ox1 = __fadd_rn(x1, off), oy1 = __fadd_rn(y1, off);
        float ox2 = __fadd_rn(x2, off), oy2 = __fadd_rn(y2, off);
        ((float4*)g_box)[gi] = make_float4(x1, y1, x2, y2);
        ((float4*)g_ob)[gi]  = make_float4(ox1, oy1, ox2, oy2);
        g_area[gi] = __fmul_rn(__fsub_rn(ox2, ox1), __fsub_rn(oy2, oy1));
    }
    lv = __reduce_add_sync(0xFFFFFFFFu, lv);
    if (lane == 0) atomicAdd(&svalid, lv);
    __syncthreads();
    if (tid == 0) g_nvalid[b] = svalid;
}

// ---------------- kernel 3: pairwise suppression mask (sparse output) ----------------
__global__ void __launch_bounds__(256) k_mask() {
    int colBlk = blockIdx.x;            // 0..63
    int rowQuad = blockIdx.y;           // 0..15 (4 row tiles each)
    int b = blockIdx.z;
    if (colBlk < rowQuad * 4) return;   // entire block below diagonal
    int t = threadIdx.x;
    int sub = t >> 6, l = t & 63;
    __shared__ float4 cb[64];
    __shared__ float  ca[64];
    __shared__ unsigned ccp[16];
    int colBase = colBlk * 64;
    if (t < 64) {
        int gj = b * TOPK + colBase + t;
        cb[t] = ((const float4*)g_ob)[gj];
        ca[t] = g_area[gj];
    } else if (t < 80) {
        ccp[t - 64] = g_clsPack[b * (TOPK / 4) + colBlk * 16 + (t - 64)];
    }
    __syncthreads();
    int rowBlk = rowQuad * 4 + sub;
    if (colBlk < rowBlk) return;        // sub-tile below diagonal (no more syncs below)
    int i = rowBlk * 64 + l;
    int gi = b * TOPK + i;
    float4 rb = ((const float4*)g_ob)[gi];
    float ra = g_area[gi];
    unsigned rc = ((const unsigned char*)g_clsPack)[gi];
    unsigned rc4 = rc * 0x01010101u;
    // branchless same-class candidate mask via packed byte compares
    unsigned lo = 0, hi = 0;
    #pragma unroll
    for (int w = 0; w < 8; ++w) {
        unsigned m = __vcmpeq4(ccp[w], rc4) & 0x01010101u;
        lo |= ((m * 0x01020408u) >> 24) << (4 * w);
    }
    #pragma unroll
    for (int w = 8; w < 16; ++w) {
        unsigned m = __vcmpeq4(ccp[w], rc4) & 0x01010101u;
        hi |= ((m * 0x01020408u) >> 24) << (4 * (w - 8));
    }
    ull cand = ((ull)hi << 32) | (ull)lo;
    if (colBlk == rowBlk) cand = (l == 63) ? 0ULL : (cand & (~0ULL << (l + 1)));
    ull bits = 0ULL;
    while (cand) {
        int c = __ffsll((long long)cand) - 1;
        cand &= cand - 1;
        float4 cc = cb[c];
        float ltx = fmaxf(rb.x, cc.x);
        float lty = fmaxf(rb.y, cc.y);
        float rbx = fminf(rb.z, cc.z);
        float rby = fminf(rb.w, cc.w);
        float wv = fmaxf(__fsub_rn(rbx, ltx), 0.0f);
        float hv = fmaxf(__fsub_rn(rby, lty), 0.0f);
        float inter = __fmul_rn(wv, hv);
        if (inter > 0.0f) {
            float denom = __fadd_rn(__fsub_rn(__fadd_rn(ra, ca[c]), inter), 1e-7f);
            if (__fdiv_rn(inter, denom) > IOU_THRES) bits |= (1ULL << c);
        }
    }
    // sparse store: only nonzero words + flag in the row bitmap
    if (bits) {
        g_mask[((size_t)b * TOPK + i) * NWORDS + colBlk] = bits;
        atomicOr(&g_rowNZ[gi], 1ULL << colBlk);
    }
}

// ------- kernel 4: sparse greedy suppression (ffs-skipping serial) + output ----------
__global__ void __launch_bounds__(128) k_suppress(float* __restrict__ out) {
    int b = blockIdx.x;
    int tid = threadIdx.x;   // 128
    __shared__ ull rowNZsh[TOPK];       // 32KB: nonzero-word bitmap for all 4096 rows
    __shared__ ull removed[NWORDS];
    __shared__ ull keepw[NWORDS];
    __shared__ ull diag[64];
    __shared__ ull sAlive;
    __shared__ unsigned sDnz[2];
    __shared__ int prefix[NWORDS];
    int nv = g_nvalid[b];
    size_t mb = (size_t)b * TOPK * NWORDS;

    // stage the full rowNZ bitmap (coalesced, once)
    #pragma unroll
    for (int t4 = tid; t4 < TOPK; t4 += 128) rowNZsh[t4] = g_rowNZ[b * TOPK + t4];
    if (tid < NWORDS) removed[tid] = 0ULL;
    __syncthreads();

    // prefetch diag tile for blk 0 (guarded by rowNZ flag; unflagged => 0)
    ull dreg = 0ULL;
    if (tid < 64 && ((rowNZsh[tid] >> 0) & 1ULL))
        dreg = g_mask[mb + (size_t)tid * NWORDS + 0];

    for (int blk = 0; blk < NWORDS; ++blk) {
        if (tid < 64) {
            diag[tid] = dreg;
            unsigned m = __ballot_sync(0xFFFFFFFFu, dreg != 0ULL);
            if ((tid & 31) == 0) sDnz[tid >> 5] = m;
        }
        __syncthreads();
        // prefetch diag tile for blk+1 during the serial phase
        if (blk + 1 < NWORDS && tid < 64) {
            int row = (blk + 1) * 64 + tid;
            dreg = ((rowNZsh[row] >> (blk + 1)) & 1ULL)
                 ? g_mask[mb + (size_t)row * NWORDS + (blk + 1)] : 0ULL;
        }
        if (tid == 0) {
            ull w = removed[blk];
            int lim = nv - blk * 64; if (lim > 64) lim = 64; if (lim < 0) lim = 0;
            ull valid = (lim >= 64) ? ~0ULL : ((lim <= 0) ? 0ULL : ((1ULL << lim) - 1ULL));
            ull dnz = ((ull)sDnz[1] << 32) | (ull)sDnz[0];
            ull alive = 0ULL;
            ull rem = ~w & valid;
            while (rem) {
                int bb = __ffsll((long long)rem) - 1;
                alive |= (1ULL << bb);
                rem &= rem - 1;                 // clear bb
                if ((dnz >> bb) & 1ULL) {
                    w |= diag[bb];
                    rem &= ~w;                  // drop newly suppressed bits
                }
            }
            keepw[blk] = alive;
            sAlive = alive;
        }
        __syncthreads();
        // OR phase: only flagged words of alive rows (tiny, sparse)
        ull alive = sAlive;
        if (tid < 64 && ((alive >> tid) & 1ULL)) {
            int row = blk * 64 + tid;
            ull wbits = (blk == 63) ? 0ULL : (rowNZsh[row] & (~0ULL << (blk + 1)));
            while (wbits) {
                int w = __ffsll((long long)wbits) - 1;
                wbits &= wbits - 1;
                ull v = g_mask[mb + (size_t)row * NWORDS + w];
                atomicOr(&removed[w], v);
            }
        }
        __syncthreads();
    }

    // ---- fused output compaction ----
    if (tid == 0) {
        int s = 0;
        for (int w = 0; w < NWORDS; ++w) { prefix[w] = s; s += __popcll(keepw[w]); }
    }
    float* o = out + (size_t)b * MAXDET * 6;
    for (int z = tid; z < MAXDET * 6; z += 128) o[z] = 0.0f;
    __syncthreads();
    for (int i = tid; i < TOPK; i += 128) {
        int w = i >> 6, bt = i & 63;
        if ((keepw[w] >> bt) & 1ULL) {
            int rank = prefix[w] + __popcll(keepw[w] & ((1ULL << bt) - 1ULL));
            if (rank < MAXDET) {
                int gi = b * TOPK + i;
                float* r = o + rank * 6;
                float4 bx = ((const float4*)g_box)[gi];
                r[0] = bx.x; r[1] = bx.y; r[2] = bx.z; r[3] = bx.w;
                r[4] = g_selScore[gi];
                r[5] = (float)g_selCls[gi];
            }
        }
    }
}

// ---------------- launch ---------------------------------------------------------------
extern "C" void kernel_launch(void* const* d_in, const int* in_sizes, int n_in,
                              void* d_out, int out_size) {
    const float* pred = (const float*)d_in[0];
    float* out = (float*)d_out;

    // 1) conf / argmax / order key : one warp per row
    {
        int rows = BATCH * NPRED;
        int threads = 256;
        int blocks = (rows * 32 + threads - 1) / threads;
        k_prep<<<blocks, threads>>>(pred);
    }
    // 2) exact top-4096 per batch + sort + fused gather (+ rowNZ zeroing)
    k_select<<<BATCH, 1024>>>(pred);
    // 3) pairwise IoU mask (sparse output)
    {
        dim3 g(NWORDS, NWORDS / 4, BATCH);
        k_mask<<<g, 256>>>();
    }
    // 4) sparse greedy suppression + fused output
    k_suppress<<<BATCH, 128>>>(out);
}

// round 6
// speedup vs baseline: 1.9276x; 1.9276x over previous
#include <cuda_runtime.h>
#include <cuda_bf16.h>
#include <cstdint>

#define BATCH   16
#define NPRED   25200
#define NC      80
#define STRIDE  85
#define TOPK    4096
#define MAXDET  1000
#define NWORDS  64            // TOPK/64
#define NITEMS  25            // ceil(NPRED/1024)
#define ECAP    2048          // per-batch sparse suppression-edge capacity
#define CONF_THRES 0.25f
#define IOU_THRES  0.45f
#define MAX_WH     7680.0f

typedef unsigned long long ull;

// ---------------- scratch (no allocation allowed; __device__ globals) ----------------
__device__ unsigned  g_u[BATCH * NPRED];        // order key (score part)
__device__ float     g_s[BATCH * NPRED];        // s = valid ? conf : -1
__device__ int       g_cls[BATCH * NPRED];      // argmax class
__device__ float     g_selScore[BATCH * TOPK];
__device__ int       g_selCls[BATCH * TOPK];
__device__ unsigned  g_clsPack[BATCH * TOPK / 4]; // classes as packed bytes
__device__ float     g_box[BATCH * TOPK * 4];   // xyxy (no offset)
__device__ float     g_ob[BATCH * TOPK * 4];    // offset boxes
__device__ float     g_area[BATCH * TOPK];      // area of offset box
__device__ ull       g_mask[(size_t)BATCH * TOPK * NWORDS]; // sparse: only flagged words valid
__device__ ull       g_rowNZ[BATCH * TOPK];     // per-row bitmap of nonzero mask words
__device__ int       g_nvalid[BATCH];
__device__ int       g_ecnt[BATCH];             // sparse edge counts
__device__ int       g_ekey[BATCH * ECAP];      // row*64 + word
__device__ ull       g_ebits[BATCH * ECAP];     // suppression bits

// ---------------- kernel 1: conf / argmax / order-key, one warp per row --------------
__global__ void k_prep(const float* __restrict__ pred) {
    int gw   = (blockIdx.x * blockDim.x + threadIdx.x) >> 5;  // global warp = row
    int lane = threadIdx.x & 31;
    if (gw >= BATCH * NPRED) return;
    const float* p = pred + (size_t)gw * STRIDE;
    float obj = p[4];
    float best = -1.0f; int bi = 0;
    #pragma unroll
    for (int c = lane; c < NC; c += 32) {
        float v = __fmul_rn(obj, p[5 + c]);
        if (v > best) { best = v; bi = c; }          // strict > keeps first max
    }
    #pragma unroll
    for (int o = 16; o; o >>= 1) {
        float b2 = __shfl_xor_sync(0xFFFFFFFFu, best, o);
        int   i2 = __shfl_xor_sync(0xFFFFFFFFu, bi, o);
        if (b2 > best || (b2 == best && i2 < bi)) { best = b2; bi = i2; }
    }
    if (lane == 0) {
        float s = (best > CONF_THRES) ? best : -1.0f;
        unsigned ub = __float_as_uint(s);
        unsigned uo = (ub & 0x80000000u) ? ~ub : (ub | 0x80000000u); // ascending order map
        g_s[gw] = s; g_u[gw] = uo; g_cls[gw] = bi;
    }
}

// ---------------- kernel 2: top-4096 (reg keys + 2-bit search) + hybrid bitonic ------
__device__ __forceinline__ ull shfl_xor_u64(ull x, int m) {
    unsigned lo = __shfl_xor_sync(0xFFFFFFFFu, (unsigned)x, m);
    unsigned hi = __shfl_xor_sync(0xFFFFFFFFu, (unsigned)(x >> 32), m);
    return ((ull)hi << 32) | lo;
}

__global__ void __launch_bounds__(1024) k_select(const float* __restrict__ pred) {
    int b = blockIdx.x;
    int tid = threadIdx.x;
    int lane = tid & 31;
    const unsigned* u = g_u + b * NPRED;
    __shared__ ull keys[TOPK];
    __shared__ ull sT;
    __shared__ int sCnt0, sCnt1, sCnt2;
    __shared__ int scnt, svalid;

    // zero per-batch side state (read by k_suppress, written by k_mask)
    #pragma unroll
    for (int t4 = tid; t4 < TOPK; t4 += 1024) g_rowNZ[b * TOPK + t4] = 0ULL;
    if (tid == 0) g_ecnt[b] = 0;

    // ---- load all keys into registers (full MLP, one pass over memory) ----
    unsigned uv[NITEMS];
    #pragma unroll
    for (int k = 0; k < NITEMS; ++k) {
        int i = k * 1024 + tid;
        uv[k] = (i < NPRED) ? u[i] : 0u;
    }
    if (tid == 0) { sT = 0ULL; sCnt0 = 0; sCnt1 = 0; sCnt2 = 0; scnt = 0; svalid = 0; }
    __syncthreads();

    // ---- 2-bit-per-step binary search for T = TOPK-th largest key ((u<<32)|~i) ----
    for (int s = 62; s >= 0; s -= 2) {
        ull T = sT;
        ull c1t = T + (1ULL << s);
        int c1 = 0, c2 = 0, c3 = 0;
        #pragma unroll
        for (int k = 0; k < NITEMS; ++k) {
            int i = k * 1024 + tid;
            if (i < NPRED) {
                ull key = ((ull)uv[k] << 32) | (unsigned)(~i);
                if (key >= c1t) {
                    ull w = (key - T) >> s;
                    c1++;
                    if (w >= 2) c2++;
                    if (w >= 3) c3++;
                }
            }
        }
        c1 = __reduce_add_sync(0xFFFFFFFFu, c1);
        c2 = __reduce_add_sync(0xFFFFFFFFu, c2);
        c3 = __reduce_add_sync(0xFFFFFFFFu, c3);
        if (lane == 0) {
            atomicAdd(&sCnt0, c1);
            atomicAdd(&sCnt1, c2);
            atomicAdd(&sCnt2, c3);
        }
        __syncthreads();
        if (tid == 0) {
            int v = (sCnt2 >= TOPK) ? 3 : (sCnt1 >= TOPK) ? 2 : (sCnt0 >= TOPK) ? 1 : 0;
            sT = T | ((ull)v << s);
            sCnt0 = 0; sCnt1 = 0; sCnt2 = 0;
        }
        __syncthreads();
    }
    ull T = sT;

    // ---- gather exactly-4096 keys >= T (warp-aggregated positions) ----
    #pragma unroll
    for (int k = 0; k < NITEMS; ++k) {
        int i = k * 1024 + tid;
        bool m = (i < NPRED);
        ull key = 0ULL;
        if (m) { key = ((ull)uv[k] << 32) | (unsigned)(~i); m = (key >= T); }
        unsigned act = __ballot_sync(0xFFFFFFFFu, m);
        if (m) {
            int leader = __ffs(act) - 1;
            int rank = __popc(act & ((1u << lane) - 1u));
            int base;
            if (lane == leader) base = atomicAdd(&scnt, __popc(act));
            base = __shfl_sync(act, base, leader);
            int pos = base + rank;
            if (pos < TOPK) keys[pos] = key;
        }
    }
    __syncthreads();

    // ---- hybrid bitonic sort, descending: 4 elems/thread (blocked) ----
    ull v[4];
    #pragma unroll
    for (int e = 0; e < 4; ++e) v[e] = keys[tid * 4 + e];

    for (int k = 2; k <= TOPK; k <<= 1) {
        for (int j = k >> 1; j >= 1; j >>= 1) {
            if (j >= 128) {
                #pragma unroll
                for (int e = 0; e < 4; ++e) keys[tid * 4 + e] = v[e];
                __syncthreads();
                #pragma unroll
                for (int e = 0; e < 4; ++e) {
                    int idx = tid * 4 + e;
                    ull pv = keys[idx ^ j];
                    bool d = ((idx & k) == 0);
                    bool lower = ((idx & j) == 0);
                    bool keepmax = (d == lower);
                    ull mx = (v[e] > pv) ? v[e] : pv;
                    ull mn = (v[e] > pv) ? pv : v[e];
                    v[e] = keepmax ? mx : mn;
                }
                __syncthreads();
            } else if (j >= 4) {
                int dl = j >> 2;
                #pragma unroll
                for (int e = 0; e < 4; ++e) {
                    ull pv = shfl_xor_u64(v[e], dl);
                    int idx = tid * 4 + e;
                    bool d = ((idx & k) == 0);
                    bool lower = ((tid & dl) == 0);
                    bool keepmax = (d == lower);
                    ull mx = (v[e] > pv) ? v[e] : pv;
                    ull mn = (v[e] > pv) ? pv : v[e];
                    v[e] = keepmax ? mx : mn;
                }
            } else {
                #pragma unroll
                for (int e = 0; e < 4; ++e) {
                    if ((e & j) == 0) {
                        int idx = tid * 4 + e;
                        bool d = ((idx & k) == 0);
                        ull a = v[e], c2 = v[e + j];
                        if (d ? (a < c2) : (a > c2)) { v[e] = c2; v[e + j] = a; }
                    }
                }
            }
        }
    }

    // ---- emit + fused gather of boxes / classes / areas ----
    int lv = 0;
    #pragma unroll
    for (int e = 0; e < 4; ++e) {
        int rank = tid * 4 + e;
        ull key = v[e];
        int i = (int)(~(unsigned)(key & 0xFFFFFFFFull));
        int gi = b * TOPK + rank;
        float s = g_s[b * NPRED + i];
        g_selScore[gi] = s;
        lv += (s > 0.0f);
        int ci = g_cls[b * NPRED + i];
        g_selCls[gi] = ci;
        ((unsigned char*)g_clsPack)[gi] = (unsigned char)ci;
        const float* p = pred + ((size_t)b * NPRED + i) * STRIDE;
        float xc = p[0], yc = p[1], w = p[2], h = p[3];
        float hw = __fmul_rn(w, 0.5f), hh = __fmul_rn(h, 0.5f);
        float x1 = __fsub_rn(xc, hw), y1 = __fsub_rn(yc, hh);
        float x2 = __fadd_rn(xc, hw), y2 = __fadd_rn(yc, hh);
        float off = __fmul_rn((float)ci, MAX_WH);
        float ox1 = __fadd_rn(x1, off), oy1 = __fadd_rn(y1, off);
        float ox2 = __fadd_rn(x2, off), oy2 = __fadd_rn(y2, off);
        ((float4*)g_box)[gi] = make_float4(x1, y1, x2, y2);
        ((float4*)g_ob)[gi]  = make_float4(ox1, oy1, ox2, oy2);
        g_area[gi] = __fmul_rn(__fsub_rn(ox2, ox1), __fsub_rn(oy2, oy1));
    }
    lv = __reduce_add_sync(0xFFFFFFFFu, lv);
    if (lane == 0) atomicAdd(&svalid, lv);
    __syncthreads();
    if (tid == 0) g_nvalid[b] = svalid;
}

// ---------------- kernel 3: pairwise suppression mask (sparse edge list) -------------
__global__ void __launch_bounds__(256) k_mask() {
    int colBlk = blockIdx.x;            // 0..63
    int rowQuad = blockIdx.y;           // 0..15 (4 row tiles each)
    int b = blockIdx.z;
    if (colBlk < rowQuad * 4) return;   // entire block below diagonal
    int t = threadIdx.x;
    int sub = t >> 6, l = t & 63;
    __shared__ float4 cb[64];
    __shared__ float  ca[64];
    __shared__ unsigned ccp[16];
    int colBase = colBlk * 64;
    if (t < 64) {
        int gj = b * TOPK + colBase + t;
        cb[t] = ((const float4*)g_ob)[gj];
        ca[t] = g_area[gj];
    } else if (t < 80) {
        ccp[t - 64] = g_clsPack[b * (TOPK / 4) + colBlk * 16 + (t - 64)];
    }
    __syncthreads();
    int rowBlk = rowQuad * 4 + sub;
    if (colBlk < rowBlk) return;        // sub-tile below diagonal (no more syncs below)
    int i = rowBlk * 64 + l;
    int gi = b * TOPK + i;
    float4 rb = ((const float4*)g_ob)[gi];
    float ra = g_area[gi];
    unsigned rc = ((const unsigned char*)g_clsPack)[gi];
    unsigned rc4 = rc * 0x01010101u;
    // branchless same-class candidate mask via packed byte compares
    unsigned lo = 0, hi = 0;
    #pragma unroll
    for (int w = 0; w < 8; ++w) {
        unsigned m = __vcmpeq4(ccp[w], rc4) & 0x01010101u;
        lo |= ((m * 0x01020408u) >> 24) << (4 * w);
    }
    #pragma unroll
    for (int w = 8; w < 16; ++w) {
        unsigned m = __vcmpeq4(ccp[w], rc4) & 0x01010101u;
        hi |= ((m * 0x01020408u) >> 24) << (4 * (w - 8));
    }
    ull cand = ((ull)hi << 32) | (ull)lo;
    if (colBlk == rowBlk) cand = (l == 63) ? 0ULL : (cand & (~0ULL << (l + 1)));
    ull bits = 0ULL;
    while (cand) {
        int c = __ffsll((long long)cand) - 1;
        cand &= cand - 1;
        float4 cc = cb[c];
        float ltx = fmaxf(rb.x, cc.x);
        float lty = fmaxf(rb.y, cc.y);
        float rbx = fminf(rb.z, cc.z);
        float rby = fminf(rb.w, cc.w);
        float wv = fmaxf(__fsub_rn(rbx, ltx), 0.0f);
        float hv = fmaxf(__fsub_rn(rby, lty), 0.0f);
        float inter = __fmul_rn(wv, hv);
        if (inter > 0.0f) {
            float denom = __fadd_rn(__fsub_rn(__fadd_rn(ra, ca[c]), inter), 1e-7f);
            if (__fdiv_rn(inter, denom) > IOU_THRES) bits |= (1ULL << c);
        }
    }
    if (bits) {
        // sparse edge list (primary path)
        int e = atomicAdd(&g_ecnt[b], 1);
        if (e < ECAP) {
            g_ekey[b * ECAP + e] = (i << 6) | colBlk;
            g_ebits[b * ECAP + e] = bits;
        }
        // dense sparse-flagged store (fallback path)
        g_mask[((size_t)b * TOPK + i) * NWORDS + colBlk] = bits;
        atomicOr(&g_rowNZ[gi], 1ULL << colBlk);
    }
}

// ------- kernel 4: sparse greedy suppression (sorted edge list) + output -------------
__global__ void __launch_bounds__(256) k_suppress(float* __restrict__ out) {
    int b = blockIdx.x;
    int tid = threadIdx.x;   // 256
    __shared__ ull pool[4096];          // 32KB: list path = sbits+skey; fallback = rowNZ
    __shared__ ull removed[NWORDS];
    __shared__ ull keepw[NWORDS];
    __shared__ ull diag[64];
    __shared__ ull sAlive;
    __shared__ unsigned sDnz[2];
    __shared__ int prefix[NWORDS];
    int nv = g_nvalid[b];
    int cnt = g_ecnt[b];
    if (tid < NWORDS) removed[tid] = 0ULL;

    if (cnt <= ECAP) {
        // ================= fast path: sorted sparse edge list =================
        ull* sbits = pool;                               // [ECAP] 16KB
        unsigned* skey = (unsigned*)(pool + ECAP);       // [ECAP] 8KB
        for (int e = tid; e < ECAP; e += 256) {
            if (e < cnt) {
                sbits[e] = g_ebits[b * ECAP + e];
                skey[e] = ((unsigned)g_ekey[b * ECAP + e] << 13) | (unsigned)e;
            } else skey[e] = 0xFFFFFFFFu;
        }
        __syncthreads();
        // bitonic ascending sort of 2048 packed keys (deterministic order)
        for (int k = 2; k <= ECAP; k <<= 1) {
            for (int j = k >> 1; j >= 1; j >>= 1) {
                for (int x = tid; x < ECAP; x += 256) {
                    int l = x ^ j;
                    if (l > x) {
                        bool asc = ((x & k) == 0);
                        unsigned a = skey[x], c = skey[l];
                        if (asc ? (a > c) : (a < c)) { skey[x] = c; skey[l] = a; }
                    }
                }
                __syncthreads();
            }
        }
        // exact greedy scan over sorted edges (single thread, all in shared)
        if (tid == 0) {
            for (int e = 0; e < cnt; ++e) {
                unsigned sv = skey[e];
                int idx = (int)(sv & 0x1FFFu);
                int key = (int)(sv >> 13);
                int row = key >> 6, word = key & 63;
                if (row >= nv) break;                    // sorted by row: done
                if (!((removed[row >> 6] >> (row & 63)) & 1ULL))
                    removed[word] |= sbits[idx];
            }
        }
        __syncthreads();
        if (tid < NWORDS) {
            int lim = nv - tid * 64; if (lim > 64) lim = 64; if (lim < 0) lim = 0;
            ull valid = (lim >= 64) ? ~0ULL : ((lim <= 0) ? 0ULL : ((1ULL << lim) - 1ULL));
            keepw[tid] = valid & ~removed[tid];
        }
        __syncthreads();
    } else {
        // ================= fallback: blocked sparse scan over g_mask =================
        ull* rowNZsh = pool;                             // [TOPK] 32KB
        size_t mb = (size_t)b * TOPK * NWORDS;
        #pragma unroll
        for (int t4 = tid; t4 < TOPK; t4 += 256) rowNZsh[t4] = g_rowNZ[b * TOPK + t4];
        __syncthreads();
        ull dreg = 0ULL;
        if (tid < 64 && ((rowNZsh[tid] >> 0) & 1ULL))
            dreg = g_mask[mb + (size_t)tid * NWORDS + 0];
        for (int blk = 0; blk < NWORDS; ++blk) {
            if (tid < 64) {
                diag[tid] = dreg;
                unsigned m = __ballot_sync(0xFFFFFFFFu, dreg != 0ULL);
                if ((tid & 31) == 0) sDnz[tid >> 5] = m;
            }
            __syncthreads();
            if (blk + 1 < NWORDS && tid < 64) {
                int row = (blk + 1) * 64 + tid;
                dreg = ((rowNZsh[row] >> (blk + 1)) & 1ULL)
                     ? g_mask[mb + (size_t)row * NWORDS + (blk + 1)] : 0ULL;
            }
            if (tid == 0) {
                ull w = removed[blk];
                int lim = nv - blk * 64; if (lim > 64) lim = 64; if (lim < 0) lim = 0;
                ull valid = (lim >= 64) ? ~0ULL : ((lim <= 0) ? 0ULL : ((1ULL << lim) - 1ULL));
                ull dnz = ((ull)sDnz[1] << 32) | (ull)sDnz[0];
                ull alive = ~w & valid;
                ull t2 = alive & dnz;
                while (t2) {
                    int bb = __ffsll((long long)t2) - 1;
                    ull d = diag[bb];
                    alive &= ~d;
                    t2 &= ~d;
                    t2 &= t2 - 1;
                }
                keepw[blk] = alive;
                sAlive = alive;
                removed[blk] = ~alive;
            }
            __syncthreads();
            ull alive = sAlive;
            if (tid < 64 && ((alive >> tid) & 1ULL)) {
                int row = blk * 64 + tid;
                ull wbits = (blk == 63) ? 0ULL : (rowNZsh[row] & (~0ULL << (blk + 1)));
                while (wbits) {
                    int w = __ffsll((long long)wbits) - 1;
                    wbits &= wbits - 1;
                    ull v = g_mask[mb + (size_t)row * NWORDS + w];
                    atomicOr(&removed[w], v);
                }
            }
            __syncthreads();
        }
    }

    // ---- fused output compaction ----
    if (tid == 0) {
        int s = 0;
        for (int w = 0; w < NWORDS; ++w) { prefix[w] = s; s += __popcll(keepw[w]); }
    }
    float* o = out + (size_t)b * MAXDET * 6;
    for (int z = tid; z < MAXDET * 6; z += 256) o[z] = 0.0f;
    __syncthreads();
    for (int i = tid; i < TOPK; i += 256) {
        int w = i >> 6, bt = i & 63;
        if ((keepw[w] >> bt) & 1ULL) {
            int rank = prefix[w] + __popcll(keepw[w] & ((1ULL << bt) - 1ULL));
            if (rank < MAXDET) {
                int gi = b * TOPK + i;
                float* r = o + rank * 6;
                float4 bx = ((const float4*)g_box)[gi];
                r[0] = bx.x; r[1] = bx.y; r[2] = bx.z; r[3] = bx.w;
                r[4] = g_selScore[gi];
                r[5] = (float)g_selCls[gi];
            }
        }
    }
}

// ---------------- launch ---------------------------------------------------------------
extern "C" void kernel_launch(void* const* d_in, const int* in_sizes, int n_in,
                              void* d_out, int out_size) {
    const float* pred = (const float*)d_in[0];
    float* out = (float*)d_out;

    // 1) conf / argmax / order key : one warp per row
    {
        int rows = BATCH * NPRED;
        int threads = 256;
        int blocks = (rows * 32 + threads - 1) / threads;
        k_prep<<<blocks, threads>>>(pred);
    }
    // 2) exact top-4096 per batch + sort + fused gather (+ per-batch state zeroing)
    k_select<<<BATCH, 1024>>>(pred);
    // 3) pairwise IoU mask -> sparse edge list (+ dense fallback store)
    {
        dim3 g(NWORDS, NWORDS / 4, BATCH);
        k_mask<<<g, 256>>>();
    }
    // 4) sparse greedy suppression + fused output
    k_suppress<<<BATCH, 256>>>(out);
}

// round 7
// speedup vs baseline: 2.2578x; 1.1713x over previous
#include <cuda_runtime.h>
#include <cuda_bf16.h>
#include <cstdint>

#define BATCH   16
#define NPRED   25200
#define NC      80
#define STRIDE  85
#define TOPK    4096
#define MAXDET  1000
#define NWORDS  64            // TOPK/64
#define NITEMS  25            // ceil(NPRED/1024)
#define ECAP    8192          // per-batch suppression-pair capacity (fast path)
#define CONF_THRES 0.25f
#define IOU_THRES  0.45f
#define MAX_WH     7680.0f

typedef unsigned long long ull;

// ---------------- scratch (no allocation allowed; __device__ globals) ----------------
__device__ unsigned  g_u[BATCH * NPRED];        // order key (score part)
__device__ float     g_s[BATCH * NPRED];        // s = valid ? conf : -1
__device__ int       g_cls[BATCH * NPRED];      // argmax class
__device__ float     g_selScore[BATCH * TOPK];
__device__ int       g_selCls[BATCH * TOPK];
__device__ float     g_box[BATCH * TOPK * 4];   // xyxy (no offset)
__device__ float     g_ob[BATCH * TOPK * 4];    // offset boxes
__device__ float     g_area[BATCH * TOPK];      // area of offset box
__device__ int       g_nvalid[BATCH];
__device__ int       g_clsCnt[BATCH * NC];      // per-class member counts
__device__ int       g_clsList[BATCH * NC * TOPK / 64 * 64]; // capacity TOPK per class
__device__ int       g_ecnt[BATCH];             // suppression pair counts
__device__ unsigned  g_epair[BATCH * ECAP];     // packed (i<<12)|j, i<j

// ---------------- kernel 1: conf / argmax / order-key, one warp per row --------------
__global__ void k_prep(const float* __restrict__ pred) {
    int gw   = (blockIdx.x * blockDim.x + threadIdx.x) >> 5;  // global warp = row
    int lane = threadIdx.x & 31;
    if (gw >= BATCH * NPRED) return;
    const float* p = pred + (size_t)gw * STRIDE;
    float obj = p[4];
    float best = -1.0f; int bi = 0;
    #pragma unroll
    for (int c = lane; c < NC; c += 32) {
        float v = __fmul_rn(obj, p[5 + c]);
        if (v > best) { best = v; bi = c; }          // strict > keeps first max
    }
    #pragma unroll
    for (int o = 16; o; o >>= 1) {
        float b2 = __shfl_xor_sync(0xFFFFFFFFu, best, o);
        int   i2 = __shfl_xor_sync(0xFFFFFFFFu, bi, o);
        if (b2 > best || (b2 == best && i2 < bi)) { best = b2; bi = i2; }
    }
    if (lane == 0) {
        float s = (best > CONF_THRES) ? best : -1.0f;
        unsigned ub = __float_as_uint(s);
        unsigned uo = (ub & 0x80000000u) ? ~ub : (ub | 0x80000000u); // ascending order map
        g_s[gw] = s; g_u[gw] = uo; g_cls[gw] = bi;
    }
}

// ---------------- kernel 2: top-4096 (reg keys + 2-bit search) + hybrid bitonic ------
__device__ __forceinline__ ull shfl_xor_u64(ull x, int m) {
    unsigned lo = __shfl_xor_sync(0xFFFFFFFFu, (unsigned)x, m);
    unsigned hi = __shfl_xor_sync(0xFFFFFFFFu, (unsigned)(x >> 32), m);
    return ((ull)hi << 32) | lo;
}

__global__ void __launch_bounds__(1024) k_select(const float* __restrict__ pred) {
    int b = blockIdx.x;
    int tid = threadIdx.x;
    int lane = tid & 31;
    const unsigned* u = g_u + b * NPRED;
    __shared__ ull keys[TOPK];
    __shared__ ull sT;
    __shared__ int sCnt0, sCnt1, sCnt2;
    __shared__ int scnt, svalid;

    // zero per-batch side state
    if (tid < NC) g_clsCnt[b * NC + tid] = 0;
    if (tid == 0) g_ecnt[b] = 0;

    // ---- load all keys into registers (full MLP, one pass over memory) ----
    unsigned uv[NITEMS];
    #pragma unroll
    for (int k = 0; k < NITEMS; ++k) {
        int i = k * 1024 + tid;
        uv[k] = (i < NPRED) ? u[i] : 0u;
    }
    if (tid == 0) { sT = 0ULL; sCnt0 = 0; sCnt1 = 0; sCnt2 = 0; scnt = 0; svalid = 0; }
    __syncthreads();

    // ---- 2-bit-per-step binary search for T = TOPK-th largest key ((u<<32)|~i) ----
    for (int s = 62; s >= 0; s -= 2) {
        ull T = sT;
        ull c1t = T + (1ULL << s);
        int c1 = 0, c2 = 0, c3 = 0;
        #pragma unroll
        for (int k = 0; k < NITEMS; ++k) {
            int i = k * 1024 + tid;
            if (i < NPRED) {
                ull key = ((ull)uv[k] << 32) | (unsigned)(~i);
                if (key >= c1t) {
                    ull w = (key - T) >> s;
                    c1++;
                    if (w >= 2) c2++;
                    if (w >= 3) c3++;
                }
            }
        }
        c1 = __reduce_add_sync(0xFFFFFFFFu, c1);
        c2 = __reduce_add_sync(0xFFFFFFFFu, c2);
        c3 = __reduce_add_sync(0xFFFFFFFFu, c3);
        if (lane == 0) {
            atomicAdd(&sCnt0, c1);
            atomicAdd(&sCnt1, c2);
            atomicAdd(&sCnt2, c3);
        }
        __syncthreads();
        if (tid == 0) {
            int v = (sCnt2 >= TOPK) ? 3 : (sCnt1 >= TOPK) ? 2 : (sCnt0 >= TOPK) ? 1 : 0;
            sT = T | ((ull)v << s);
            sCnt0 = 0; sCnt1 = 0; sCnt2 = 0;
        }
        __syncthreads();
    }
    ull T = sT;

    // ---- gather exactly-4096 keys >= T (warp-aggregated positions) ----
    #pragma unroll
    for (int k = 0; k < NITEMS; ++k) {
        int i = k * 1024 + tid;
        bool m = (i < NPRED);
        ull key = 0ULL;
        if (m) { key = ((ull)uv[k] << 32) | (unsigned)(~i); m = (key >= T); }
        unsigned act = __ballot_sync(0xFFFFFFFFu, m);
        if (m) {
            int leader = __ffs(act) - 1;
            int rank = __popc(act & ((1u << lane) - 1u));
            int base;
            if (lane == leader) base = atomicAdd(&scnt, __popc(act));
            base = __shfl_sync(act, base, leader);
            int pos = base + rank;
            if (pos < TOPK) keys[pos] = key;
        }
    }
    __syncthreads();

    // ---- hybrid bitonic sort, descending: 4 elems/thread (blocked) ----
    ull v[4];
    #pragma unroll
    for (int e = 0; e < 4; ++e) v[e] = keys[tid * 4 + e];

    for (int k = 2; k <= TOPK; k <<= 1) {
        for (int j = k >> 1; j >= 1; j >>= 1) {
            if (j >= 128) {
                #pragma unroll
                for (int e = 0; e < 4; ++e) keys[tid * 4 + e] = v[e];
                __syncthreads();
                #pragma unroll
                for (int e = 0; e < 4; ++e) {
                    int idx = tid * 4 + e;
                    ull pv = keys[idx ^ j];
                    bool d = ((idx & k) == 0);
                    bool lower = ((idx & j) == 0);
                    bool keepmax = (d == lower);
                    ull mx = (v[e] > pv) ? v[e] : pv;
                    ull mn = (v[e] > pv) ? pv : v[e];
                    v[e] = keepmax ? mx : mn;
                }
                __syncthreads();
            } else if (j >= 4) {
                int dl = j >> 2;
                #pragma unroll
                for (int e = 0; e < 4; ++e) {
                    ull pv = shfl_xor_u64(v[e], dl);
                    int idx = tid * 4 + e;
                    bool d = ((idx & k) == 0);
                    bool lower = ((tid & dl) == 0);
                    bool keepmax = (d == lower);
                    ull mx = (v[e] > pv) ? v[e] : pv;
                    ull mn = (v[e] > pv) ? pv : v[e];
                    v[e] = keepmax ? mx : mn;
                }
            } else {
                #pragma unroll
                for (int e = 0; e < 4; ++e) {
                    if ((e & j) == 0) {
                        int idx = tid * 4 + e;
                        bool d = ((idx & k) == 0);
                        ull a = v[e], c2 = v[e + j];
                        if (d ? (a < c2) : (a > c2)) { v[e] = c2; v[e + j] = a; }
                    }
                }
            }
        }
    }

    // ---- emit + fused gather of boxes / classes / areas + class bucketing ----
    int lv = 0;
    #pragma unroll
    for (int e = 0; e < 4; ++e) {
        int rank = tid * 4 + e;
        ull key = v[e];
        int i = (int)(~(unsigned)(key & 0xFFFFFFFFull));
        int gi = b * TOPK + rank;
        float s = g_s[b * NPRED + i];
        g_selScore[gi] = s;
        lv += (s > 0.0f);
        int ci = g_cls[b * NPRED + i];
        g_selCls[gi] = ci;
        int slot = atomicAdd(&g_clsCnt[b * NC + ci], 1);
        g_clsList[(b * NC + ci) * TOPK + slot] = rank;
        const float* p = pred + ((size_t)b * NPRED + i) * STRIDE;
        float xc = p[0], yc = p[1], w = p[2], h = p[3];
        float hw = __fmul_rn(w, 0.5f), hh = __fmul_rn(h, 0.5f);
        float x1 = __fsub_rn(xc, hw), y1 = __fsub_rn(yc, hh);
        float x2 = __fadd_rn(xc, hw), y2 = __fadd_rn(yc, hh);
        float off = __fmul_rn((float)ci, MAX_WH);
        float ox1 = __fadd_rn(x1, off), oy1 = __fadd_rn(y1, off);
        float ox2 = __fadd_rn(x2, off), oy2 = __fadd_rn(y2, off);
        ((float4*)g_box)[gi] = make_float4(x1, y1, x2, y2);
        ((float4*)g_ob)[gi]  = make_float4(ox1, oy1, ox2, oy2);
        g_area[gi] = __fmul_rn(__fsub_rn(ox2, ox1), __fsub_rn(oy2, oy1));
    }
    lv = __reduce_add_sync(0xFFFFFFFFu, lv);
    if (lane == 0) atomicAdd(&svalid, lv);
    __syncthreads();
    if (tid == 0) g_nvalid[b] = svalid;
}

// ------------- kernel 3: per-class pairwise IoU -> suppression pair list -------------
__device__ __forceinline__ bool iou_exceeds(const float4& A, float aA,
                                            const float4& B, float aB) {
    float ltx = fmaxf(A.x, B.x);
    float lty = fmaxf(A.y, B.y);
    float rbx = fminf(A.z, B.z);
    float rby = fminf(A.w, B.w);
    float wv = fmaxf(__fsub_rn(rbx, ltx), 0.0f);
    float hv = fmaxf(__fsub_rn(rby, lty), 0.0f);
    float inter = __fmul_rn(wv, hv);
    if (inter <= 0.0f) return false;
    float denom = __fadd_rn(__fsub_rn(__fadd_rn(aA, aB), inter), 1e-7f);
    return __fdiv_rn(inter, denom) > IOU_THRES;
}

__global__ void __launch_bounds__(256) k_mask() {
    int c = blockIdx.x;     // class
    int b = blockIdx.y;     // batch
    int tid = threadIdx.x;
    __shared__ int list[TOPK];  // member ranks (unordered)
    int n = g_clsCnt[b * NC + c];
    if (n < 2) return;
    const int* gl = g_clsList + (b * NC + c) * TOPK;
    for (int s = tid; s < n; s += 256) list[s] = gl[s];
    __syncthreads();
    long long total = (long long)n * (n - 1) / 2;
    for (long long p = tid; p < total; p += 256) {
        // map p -> (a,bq) in upper triangle, row-major: p = f(a) + (bq - a - 1),
        // f(a) = a*n - a*(a+1)/2
        float fn = (float)n;
        float pf = (float)p;
        int a = (int)(fn - 0.5f - sqrtf(fmaxf((fn - 0.5f) * (fn - 0.5f) - 2.0f * pf, 0.0f)));
        if (a < 0) a = 0; if (a > n - 2) a = n - 2;
        // exact integer fixup
        while ((long long)(a + 1) * n - (long long)(a + 1) * (a + 2) / 2 <= p) a++;
        while ((long long)a * n - (long long)a * (a + 1) / 2 > p) a--;
        long long fa = (long long)a * n - (long long)a * (a + 1) / 2;
        int bq = (int)(p - fa) + a + 1;
        int r1 = list[a], r2 = list[bq];
        int i = min(r1, r2), j = max(r1, r2);
        int gi = b * TOPK + i, gj = b * TOPK + j;
        float4 A = ((const float4*)g_ob)[gi];
        float4 B = ((const float4*)g_ob)[gj];
        if (iou_exceeds(A, g_area[gi], B, g_area[gj])) {
            int e = atomicAdd(&g_ecnt[b], 1);
            if (e < ECAP) g_epair[b * ECAP + e] = ((unsigned)i << 12) | (unsigned)j;
        }
    }
}

// ------- kernel 4: greedy suppression over sorted pair list + fused output -----------
__global__ void __launch_bounds__(256) k_suppress(float* __restrict__ out) {
    int b = blockIdx.x;
    int tid = threadIdx.x;   // 256
    __shared__ unsigned skey[ECAP];     // 32KB
    __shared__ ull removed[NWORDS];
    __shared__ ull keepw[NWORDS];
    __shared__ int prefix[NWORDS];
    int nv = g_nvalid[b];
    int cnt = g_ecnt[b];
    if (tid < NWORDS) removed[tid] = 0ULL;

    if (cnt <= ECAP) {
        // ---- fast path: sort packed pairs ascending, serial greedy scan ----
        int n = 2;
        while (n < cnt) n <<= 1;          // smallest pow2 >= cnt
        for (int e = tid; e < n; e += 256)
            skey[e] = (e < cnt) ? g_epair[b * ECAP + e] : 0xFFFFFFFFu;
        __syncthreads();
        for (int k = 2; k <= n; k <<= 1) {
            for (int j = k >> 1; j >= 1; j >>= 1) {
                for (int x = tid; x < n; x += 256) {
                    int l = x ^ j;
                    if (l > x) {
                        bool asc = ((x & k) == 0);
                        unsigned a = skey[x], c = skey[l];
                        if (asc ? (a > c) : (a < c)) { skey[x] = c; skey[l] = a; }
                    }
                }
                __syncthreads();
            }
        }
        if (tid == 0) {
            for (int e = 0; e < cnt; ++e) {
                unsigned k = skey[e];
                int i = (int)(k >> 12);
                if (i >= nv) break;                      // sorted by i: done
                if (!((removed[i >> 6] >> (i & 63)) & 1ULL)) {
                    int j = (int)(k & 4095u);
                    removed[j >> 6] |= (1ULL << (j & 63));
                }
            }
        }
        __syncthreads();
    } else {
        // ---- fallback (never expected): exact serial greedy from class lists ----
        if (tid == 0) {
            for (int i = 0; i < nv; ++i) {
                if ((removed[i >> 6] >> (i & 63)) & 1ULL) continue;
                int c = g_selCls[b * TOPK + i];
                int n = g_clsCnt[b * NC + c];
                const int* gl = g_clsList + (b * NC + c) * TOPK;
                float4 A = ((const float4*)g_ob)[b * TOPK + i];
                float aA = g_area[b * TOPK + i];
                for (int s = 0; s < n; ++s) {
                    int j = gl[s];
                    if (j <= i) continue;
                    if ((removed[j >> 6] >> (j & 63)) & 1ULL) continue;
                    float4 B = ((const float4*)g_ob)[b * TOPK + j];
                    if (iou_exceeds(A, aA, B, g_area[b * TOPK + j]))
                        removed[j >> 6] |= (1ULL << (j & 63));
                }
            }
        }
        __syncthreads();
    }

    if (tid < NWORDS) {
        int lim = nv - tid * 64; if (lim > 64) lim = 64; if (lim < 0) lim = 0;
        ull valid = (lim >= 64) ? ~0ULL : ((lim <= 0) ? 0ULL : ((1ULL << lim) - 1ULL));
        keepw[tid] = valid & ~removed[tid];
    }
    __syncthreads();

    // ---- fused output compaction ----
    if (tid == 0) {
        int s = 0;
        for (int w = 0; w < NWORDS; ++w) { prefix[w] = s; s += __popcll(keepw[w]); }
    }
    float* o = out + (size_t)b * MAXDET * 6;
    for (int z = tid; z < MAXDET * 6; z += 256) o[z] = 0.0f;
    __syncthreads();
    for (int i = tid; i < TOPK; i += 256) {
        int w = i >> 6, bt = i & 63;
        if ((keepw[w] >> bt) & 1ULL) {
            int rank = prefix[w] + __popcll(keepw[w] & ((1ULL << bt) - 1ULL));
            if (rank < MAXDET) {
                int gi = b * TOPK + i;
                float* r = o + rank * 6;
                float4 bx = ((const float4*)g_box)[gi];
                r[0] = bx.x; r[1] = bx.y; r[2] = bx.z; r[3] = bx.w;
                r[4] = g_selScore[gi];
                r[5] = (float)g_selCls[gi];
            }
        }
    }
}

// ---------------- launch ---------------------------------------------------------------
extern "C" void kernel_launch(void* const* d_in, const int* in_sizes, int n_in,
                              void* d_out, int out_size) {
    const float* pred = (const float*)d_in[0];
    float* out = (float*)d_out;

    // 1) conf / argmax / order key : one warp per row
    {
        int rows = BATCH * NPRED;
        int threads = 256;
        int blocks = (rows * 32 + threads - 1) / threads;
        k_prep<<<blocks, threads>>>(pred);
    }
    // 2) exact top-4096 per batch + sort + fused gather + class bucketing
    k_select<<<BATCH, 1024>>>(pred);
    // 3) per-class pairwise IoU -> suppression pairs
    {
        dim3 g(NC, BATCH);
        k_mask<<<g, 256>>>();
    }
    // 4) greedy suppression + fused output
    k_suppress<<<BATCH, 256>>>(out);
}

// round 8
// speedup vs baseline: 2.6406x; 1.1695x over previous
#include <cuda_runtime.h>
#include <cuda_bf16.h>
#include <cstdint>

#define BATCH   16
#define NPRED   25200
#define NC      80
#define STRIDE  85
#define TOPK    4096
#define MAXDET  1000
#define NWORDS  64            // TOPK/64
#define NITEMS  25            // ceil(NPRED/1024)
#define ECAP    8192          // per-batch suppression-pair capacity (fast path)
#define CONF_THRES 0.25f
#define IOU_THRES  0.45f
#define MAX_WH     7680.0f

typedef unsigned long long ull;

// ---------------- scratch (no allocation allowed; __device__ globals) ----------------
__device__ unsigned  g_u[BATCH * NPRED];        // order key (score part)
__device__ float     g_s[BATCH * NPRED];        // s = valid ? conf : -1
__device__ int       g_cls[BATCH * NPRED];      // argmax class
__device__ float     g_selScore[BATCH * TOPK];
__device__ int       g_selCls[BATCH * TOPK];
__device__ float     g_box[BATCH * TOPK * 4];   // xyxy (no offset)
__device__ float     g_ob[BATCH * TOPK * 4];    // offset boxes
__device__ float     g_area[BATCH * TOPK];      // area of offset box
__device__ int       g_nvalid[BATCH];
__device__ int       g_clsCnt[BATCH * NC];      // per-class member counts
__device__ int       g_clsList[BATCH * NC * TOPK / 64 * 64]; // capacity TOPK per class
__device__ int       g_ecnt[BATCH];             // suppression pair counts
__device__ unsigned  g_epair[BATCH * ECAP];     // packed (i<<12)|j, i<j

// ---------------- kernel 1: conf / argmax / order-key, one warp per row --------------
__global__ void k_prep(const float* __restrict__ pred) {
    int gw   = (blockIdx.x * blockDim.x + threadIdx.x) >> 5;  // global warp = row
    int lane = threadIdx.x & 31;
    if (gw >= BATCH * NPRED) return;
    const float* p = pred + (size_t)gw * STRIDE;
    float obj = p[4];
    float best = -1.0f; int bi = 0;
    #pragma unroll
    for (int c = lane; c < NC; c += 32) {
        float v = __fmul_rn(obj, p[5 + c]);
        if (v > best) { best = v; bi = c; }          // strict > keeps first max
    }
    #pragma unroll
    for (int o = 16; o; o >>= 1) {
        float b2 = __shfl_xor_sync(0xFFFFFFFFu, best, o);
        int   i2 = __shfl_xor_sync(0xFFFFFFFFu, bi, o);
        if (b2 > best || (b2 == best && i2 < bi)) { best = b2; bi = i2; }
    }
    if (lane == 0) {
        float s = (best > CONF_THRES) ? best : -1.0f;
        unsigned ub = __float_as_uint(s);
        unsigned uo = (ub & 0x80000000u) ? ~ub : (ub | 0x80000000u); // ascending order map
        g_s[gw] = s; g_u[gw] = uo; g_cls[gw] = bi;
    }
}

// ---------------- kernel 2: top-4096 (32-bit search + tie index search) --------------
__device__ __forceinline__ ull shfl_xor_u64(ull x, int m) {
    unsigned lo = __shfl_xor_sync(0xFFFFFFFFu, (unsigned)x, m);
    unsigned hi = __shfl_xor_sync(0xFFFFFFFFu, (unsigned)(x >> 32), m);
    return ((ull)hi << 32) | lo;
}

#define NIT_U   16   // 2-bit steps over 32-bit u
#define NIT_I   15   // 1-bit steps over 15-bit index
// counter layout: [0..47] u-search (3 per iter), [48] C_gt, [49..63] index search
#define CNT_TOTAL 64

__global__ void __launch_bounds__(1024) k_select(const float* __restrict__ pred) {
    int b = blockIdx.x;
    int tid = threadIdx.x;
    int lane = tid & 31;
    const unsigned* u = g_u + b * NPRED;
    __shared__ ull keys[TOPK];
    __shared__ int cnts[CNT_TOTAL];
    __shared__ int scnt, svalid;

    // zero per-batch side state
    if (tid < NC) g_clsCnt[b * NC + tid] = 0;
    if (tid == 0) { g_ecnt[b] = 0; scnt = 0; svalid = 0; }
    if (tid < CNT_TOTAL) cnts[tid] = 0;

    // ---- load all keys into registers (full MLP, one pass over memory) ----
    unsigned uv[NITEMS];
    #pragma unroll
    for (int k = 0; k < NITEMS; ++k) {
        int i = k * 1024 + tid;
        uv[k] = (i < NPRED) ? u[i] : 0u;   // fake items get u=0 (never counted/selected)
    }
    __syncthreads();

    // ---- 2-bit-per-step search for u* = u-word of the 4096th-largest key ----
    unsigned U = 0u;           // identical in every thread
    #pragma unroll
    for (int it = 0; it < NIT_U; ++it) {
        int s = 30 - 2 * it;
        unsigned c1t = U + (1u << s);
        int c1 = 0, c2 = 0, c3 = 0;
        #pragma unroll
        for (int k = 0; k < NITEMS; ++k) {
            unsigned k0 = uv[k];
            if (k0 >= c1t) {
                unsigned w = (k0 - U) >> s;
                c1++;
                if (w >= 2) c2++;
                if (w >= 3) c3++;
            }
        }
        c1 = __reduce_add_sync(0xFFFFFFFFu, c1);
        c2 = __reduce_add_sync(0xFFFFFFFFu, c2);
        c3 = __reduce_add_sync(0xFFFFFFFFu, c3);
        if (lane == 0) {
            atomicAdd(&cnts[it * 3 + 0], c1);
            atomicAdd(&cnts[it * 3 + 1], c2);
            atomicAdd(&cnts[it * 3 + 2], c3);
        }
        __syncthreads();
        int t1 = cnts[it * 3 + 0], t2 = cnts[it * 3 + 1], t3 = cnts[it * 3 + 2];
        unsigned v = (t3 >= TOPK) ? 3u : (t2 >= TOPK) ? 2u : (t1 >= TOPK) ? 1u : 0u;
        U |= v << s;           // every thread computes the same update: no 2nd sync
    }
    unsigned ustar = U;

    // ---- C_gt = count(u > u*) ----
    {
        int c = 0;
        #pragma unroll
        for (int k = 0; k < NITEMS; ++k) c += (uv[k] > ustar);
        c = __reduce_add_sync(0xFFFFFFFFu, c);
        if (lane == 0) atomicAdd(&cnts[48], c);
        __syncthreads();
    }
    int need = TOPK - cnts[48];   // >= 1

    // ---- 15-bit search: M = largest x with #{u==u* && i<x} < need ----
    int M = 0;
    #pragma unroll
    for (int it = 0; it < NIT_I; ++it) {
        int bit = 14 - it;
        int cand = M | (1 << bit);
        int c = 0;
        #pragma unroll
        for (int k = 0; k < NITEMS; ++k) {
            int i = k * 1024 + tid;
            if (uv[k] == ustar && i < cand && i < NPRED) c++;
        }
        c = __reduce_add_sync(0xFFFFFFFFu, c);
        if (lane == 0) atomicAdd(&cnts[49 + it], c);
        __syncthreads();
        if (cnts[49 + it] < need) M = cand;   // same decision in every thread
    }
    // selection predicate: (u > u*) || (u == u* && i <= M)  -> exactly TOPK items

    // ---- gather exactly-4096 keys (warp-aggregated positions) ----
    #pragma unroll
    for (int k = 0; k < NITEMS; ++k) {
        int i = k * 1024 + tid;
        unsigned k0 = uv[k];
        bool m = (i < NPRED) && (k0 > ustar || (k0 == ustar && i <= M));
        unsigned act = __ballot_sync(0xFFFFFFFFu, m);
        if (m) {
            int leader = __ffs(act) - 1;
            int rank = __popc(act & ((1u << lane) - 1u));
            int base;
            if (lane == leader) base = atomicAdd(&scnt, __popc(act));
            base = __shfl_sync(act, base, leader);
            int pos = base + rank;
            if (pos < TOPK) keys[pos] = ((ull)k0 << 32) | (unsigned)(~i);
        }
    }
    __syncthreads();

    // ---- hybrid bitonic sort, descending: 4 elems/thread (blocked) ----
    ull v[4];
    #pragma unroll
    for (int e = 0; e < 4; ++e) v[e] = keys[tid * 4 + e];

    for (int k = 2; k <= TOPK; k <<= 1) {
        for (int j = k >> 1; j >= 1; j >>= 1) {
            if (j >= 128) {
                #pragma unroll
                for (int e = 0; e < 4; ++e) keys[tid * 4 + e] = v[e];
                __syncthreads();
                #pragma unroll
                for (int e = 0; e < 4; ++e) {
                    int idx = tid * 4 + e;
                    ull pv = keys[idx ^ j];
                    bool d = ((idx & k) == 0);
                    bool lower = ((idx & j) == 0);
                    bool keepmax = (d == lower);
                    ull mx = (v[e] > pv) ? v[e] : pv;
                    ull mn = (v[e] > pv) ? pv : v[e];
                    v[e] = keepmax ? mx : mn;
                }
                __syncthreads();
            } else if (j >= 4) {
                int dl = j >> 2;
                #pragma unroll
                for (int e = 0; e < 4; ++e) {
                    ull pv = shfl_xor_u64(v[e], dl);
                    int idx = tid * 4 + e;
                    bool d = ((idx & k) == 0);
                    bool lower = ((tid & dl) == 0);
                    bool keepmax = (d == lower);
                    ull mx = (v[e] > pv) ? v[e] : pv;
                    ull mn = (v[e] > pv) ? pv : v[e];
                    v[e] = keepmax ? mx : mn;
                }
            } else {
                #pragma unroll
                for (int e = 0; e < 4; ++e) {
                    if ((e & j) == 0) {
                        int idx = tid * 4 + e;
                        bool d = ((idx & k) == 0);
                        ull a = v[e], c2 = v[e + j];
                        if (d ? (a < c2) : (a > c2)) { v[e] = c2; v[e + j] = a; }
                    }
                }
            }
        }
    }

    // ---- emit + fused gather of boxes / classes / areas + class bucketing ----
    int lv = 0;
    #pragma unroll
    for (int e = 0; e < 4; ++e) {
        int rank = tid * 4 + e;
        ull key = v[e];
        int i = (int)(~(unsigned)(key & 0xFFFFFFFFull));
        int gi = b * TOPK + rank;
        float s = g_s[b * NPRED + i];
        g_selScore[gi] = s;
        lv += (s > 0.0f);
        int ci = g_cls[b * NPRED + i];
        g_selCls[gi] = ci;
        int slot = atomicAdd(&g_clsCnt[b * NC + ci], 1);
        g_clsList[(b * NC + ci) * TOPK + slot] = rank;
        const float* p = pred + ((size_t)b * NPRED + i) * STRIDE;
        float xc = p[0], yc = p[1], w = p[2], h = p[3];
        float hw = __fmul_rn(w, 0.5f), hh = __fmul_rn(h, 0.5f);
        float x1 = __fsub_rn(xc, hw), y1 = __fsub_rn(yc, hh);
        float x2 = __fadd_rn(xc, hw), y2 = __fadd_rn(yc, hh);
        float off = __fmul_rn((float)ci, MAX_WH);
        float ox1 = __fadd_rn(x1, off), oy1 = __fadd_rn(y1, off);
        float ox2 = __fadd_rn(x2, off), oy2 = __fadd_rn(y2, off);
        ((float4*)g_box)[gi] = make_float4(x1, y1, x2, y2);
        ((float4*)g_ob)[gi]  = make_float4(ox1, oy1, ox2, oy2);
        g_area[gi] = __fmul_rn(__fsub_rn(ox2, ox1), __fsub_rn(oy2, oy1));
    }
    lv = __reduce_add_sync(0xFFFFFFFFu, lv);
    if (lane == 0) atomicAdd(&svalid, lv);
    __syncthreads();
    if (tid == 0) g_nvalid[b] = svalid;
}

// ------------- kernel 3: per-class pairwise IoU -> suppression pair list -------------
__device__ __forceinline__ bool iou_exceeds(const float4& A, float aA,
                                            const float4& B, float aB) {
    float ltx = fmaxf(A.x, B.x);
    float lty = fmaxf(A.y, B.y);
    float rbx = fminf(A.z, B.z);
    float rby = fminf(A.w, B.w);
    float wv = fmaxf(__fsub_rn(rbx, ltx), 0.0f);
    float hv = fmaxf(__fsub_rn(rby, lty), 0.0f);
    float inter = __fmul_rn(wv, hv);
    if (inter <= 0.0f) return false;
    float denom = __fadd_rn(__fsub_rn(__fadd_rn(aA, aB), inter), 1e-7f);
    return __fdiv_rn(inter, denom) > IOU_THRES;
}

__global__ void __launch_bounds__(256) k_mask() {
    int c = blockIdx.x;     // class
    int b = blockIdx.y;     // batch
    int tid = threadIdx.x;
    __shared__ int list[TOPK];  // member ranks (unordered)
    int n = g_clsCnt[b * NC + c];
    if (n < 2) return;
    const int* gl = g_clsList + (b * NC + c) * TOPK;
    for (int s = tid; s < n; s += 256) list[s] = gl[s];
    __syncthreads();
    long long total = (long long)n * (n - 1) / 2;
    for (long long p = tid; p < total; p += 256) {
        float fn = (float)n;
        float pf = (float)p;
        int a = (int)(fn - 0.5f - sqrtf(fmaxf((fn - 0.5f) * (fn - 0.5f) - 2.0f * pf, 0.0f)));
        if (a < 0) a = 0; if (a > n - 2) a = n - 2;
        while ((long long)(a + 1) * n - (long long)(a + 1) * (a + 2) / 2 <= p) a++;
        while ((long long)a * n - (long long)a * (a + 1) / 2 > p) a--;
        long long fa = (long long)a * n - (long long)a * (a + 1) / 2;
        int bq = (int)(p - fa) + a + 1;
        int r1 = list[a], r2 = list[bq];
        int i = min(r1, r2), j = max(r1, r2);
        int gi = b * TOPK + i, gj = b * TOPK + j;
        float4 A = ((const float4*)g_ob)[gi];
        float4 B = ((const float4*)g_ob)[gj];
        if (iou_exceeds(A, g_area[gi], B, g_area[gj])) {
            int e = atomicAdd(&g_ecnt[b], 1);
            if (e < ECAP) g_epair[b * ECAP + e] = ((unsigned)i << 12) | (unsigned)j;
        }
    }
}

// ------- kernel 4: greedy suppression over sorted pair list + fused output -----------
__global__ void __launch_bounds__(256) k_suppress(float* __restrict__ out) {
    int b = blockIdx.x;
    int tid = threadIdx.x;   // 256
    __shared__ unsigned skey[ECAP];     // 32KB
    __shared__ ull removed[NWORDS];
    __shared__ ull keepw[NWORDS];
    __shared__ int prefix[NWORDS];
    int nv = g_nvalid[b];
    int cnt = g_ecnt[b];
    if (tid < NWORDS) removed[tid] = 0ULL;

    if (cnt <= ECAP) {
        // ---- fast path: sort packed pairs ascending, serial greedy scan ----
        int n = 2;
        while (n < cnt) n <<= 1;          // smallest pow2 >= cnt
        for (int e = tid; e < n; e += 256)
            skey[e] = (e < cnt) ? g_epair[b * ECAP + e] : 0xFFFFFFFFu;
        __syncthreads();
        for (int k = 2; k <= n; k <<= 1) {
            for (int j = k >> 1; j >= 1; j >>= 1) {
                for (int x = tid; x < n; x += 256) {
                    int l = x ^ j;
                    if (l > x) {
                        bool asc = ((x & k) == 0);
                        unsigned a = skey[x], c = skey[l];
                        if (asc ? (a > c) : (a < c)) { skey[x] = c; skey[l] = a; }
                    }
                }
                __syncthreads();
            }
        }
        if (tid == 0) {
            for (int e = 0; e < cnt; ++e) {
                unsigned k = skey[e];
                int i = (int)(k >> 12);
                if (i >= nv) break;                      // sorted by i: done
                if (!((removed[i >> 6] >> (i & 63)) & 1ULL)) {
                    int j = (int)(k & 4095u);
                    removed[j >> 6] |= (1ULL << (j & 63));
                }
            }
        }
        __syncthreads();
    } else {
        // ---- fallback (never expected): exact serial greedy from class lists ----
        if (tid == 0) {
            for (int i = 0; i < nv; ++i) {
                if ((removed[i >> 6] >> (i & 63)) & 1ULL) continue;
                int c = g_selCls[b * TOPK + i];
                int n = g_clsCnt[b * NC + c];
                const int* gl = g_clsList + (b * NC + c) * TOPK;
                float4 A = ((const float4*)g_ob)[b * TOPK + i];
                float aA = g_area[b * TOPK + i];
                for (int s = 0; s < n; ++s) {
                    int j = gl[s];
                    if (j <= i) continue;
                    if ((removed[j >> 6] >> (j & 63)) & 1ULL) continue;
                    float4 B = ((const float4*)g_ob)[b * TOPK + j];
                    if (iou_exceeds(A, aA, B, g_area[b * TOPK + j]))
                        removed[j >> 6] |= (1ULL << (j & 63));
                }
            }
        }
        __syncthreads();
    }

    if (tid < NWORDS) {
        int lim = nv - tid * 64; if (lim > 64) lim = 64; if (lim < 0) lim = 0;
        ull valid = (lim >= 64) ? ~0ULL : ((lim <= 0) ? 0ULL : ((1ULL << lim) - 1ULL));
        keepw[tid] = valid & ~removed[tid];
    }
    __syncthreads();

    // ---- fused output compaction ----
    if (tid == 0) {
        int s = 0;
        for (int w = 0; w < NWORDS; ++w) { prefix[w] = s; s += __popcll(keepw[w]); }
    }
    float* o = out + (size_t)b * MAXDET * 6;
    for (int z = tid; z < MAXDET * 6; z += 256) o[z] = 0.0f;
    __syncthreads();
    for (int i = tid; i < TOPK; i += 256) {
        int w = i >> 6, bt = i & 63;
        if ((keepw[w] >> bt) & 1ULL) {
            int rank = prefix[w] + __popcll(keepw[w] & ((1ULL << bt) - 1ULL));
            if (rank < MAXDET) {
                int gi = b * TOPK + i;
                float* r = o + rank * 6;
                float4 bx = ((const float4*)g_box)[gi];
                r[0] = bx.x; r[1] = bx.y; r[2] = bx.z; r[3] = bx.w;
                r[4] = g_selScore[gi];
                r[5] = (float)g_selCls[gi];
            }
        }
    }
}

// ---------------- launch ---------------------------------------------------------------
extern "C" void kernel_launch(void* const* d_in, const int* in_sizes, int n_in,
                              void* d_out, int out_size) {
    const float* pred = (const float*)d_in[0];
    float* out = (float*)d_out;

    // 1) conf / argmax / order key : one warp per row
    {
        int rows = BATCH * NPRED;
        int threads = 256;
        int blocks = (rows * 32 + threads - 1) / threads;
        k_prep<<<blocks, threads>>>(pred);
    }
    // 2) exact top-4096 per batch + sort + fused gather + class bucketing
    k_select<<<BATCH, 1024>>>(pred);
    // 3) per-class pairwise IoU -> suppression pairs
    {
        dim3 g(NC, BATCH);
        k_mask<<<g, 256>>>();
    }
    // 4) greedy suppression + fused output
    k_suppress<<<BATCH, 256>>>(out);
}

// round 9
// speedup vs baseline: 2.8158x; 1.0664x over previous
#include <cuda_runtime.h>
#include <cuda_bf16.h>
#include <cstdint>

#define BATCH   16
#define NPRED   25200
#define NC      80
#define STRIDE  85
#define TOPK    4096
#define MAXDET  1000
#define NWORDS  64            // TOPK/64
#define NITEMS  25            // ceil(NPRED/1024)
#define ECAP    8192          // per-batch suppression-pair capacity (fast path)
#define MCACHE  1024          // k_mask shared box-cache capacity
#define CONF_THRES 0.25f
#define IOU_THRES  0.45f
#define MAX_WH     7680.0f

typedef unsigned long long ull;

// ---------------- scratch (no allocation allowed; __device__ globals) ----------------
__device__ unsigned  g_u[BATCH * NPRED];        // order key (score part)
__device__ float     g_s[BATCH * NPRED];        // s = valid ? conf : -1
__device__ int       g_cls[BATCH * NPRED];      // argmax class
__device__ float     g_selScore[BATCH * TOPK];
__device__ int       g_selCls[BATCH * TOPK];
__device__ float     g_box[BATCH * TOPK * 4];   // xyxy (no offset)
__device__ float     g_ob[BATCH * TOPK * 4];    // offset boxes
__device__ float     g_area[BATCH * TOPK];      // area of offset box
__device__ int       g_nvalid[BATCH];
__device__ int       g_clsCnt[BATCH * NC];      // per-class member counts
__device__ int       g_clsList[BATCH * NC * TOPK / 64 * 64]; // capacity TOPK per class
__device__ int       g_ecnt[BATCH];             // suppression pair counts
__device__ unsigned  g_epair[BATCH * ECAP];     // packed (i<<12)|j, i<j

// ---------------- kernel 1: conf / argmax / order-key, one warp per row --------------
__global__ void k_prep(const float* __restrict__ pred) {
    int gw   = (blockIdx.x * blockDim.x + threadIdx.x) >> 5;  // global warp = row
    int lane = threadIdx.x & 31;
    if (gw >= BATCH * NPRED) return;
    const float* p = pred + (size_t)gw * STRIDE;
    float obj = p[4];
    float best = -1.0f; int bi = 0;
    #pragma unroll
    for (int c = lane; c < NC; c += 32) {
        float v = __fmul_rn(obj, p[5 + c]);
        if (v > best) { best = v; bi = c; }          // strict > keeps first max
    }
    #pragma unroll
    for (int o = 16; o; o >>= 1) {
        float b2 = __shfl_xor_sync(0xFFFFFFFFu, best, o);
        int   i2 = __shfl_xor_sync(0xFFFFFFFFu, bi, o);
        if (b2 > best || (b2 == best && i2 < bi)) { best = b2; bi = i2; }
    }
    if (lane == 0) {
        float s = (best > CONF_THRES) ? best : -1.0f;
        unsigned ub = __float_as_uint(s);
        unsigned uo = (ub & 0x80000000u) ? ~ub : (ub | 0x80000000u); // ascending order map
        g_s[gw] = s; g_u[gw] = uo; g_cls[gw] = bi;
    }
}

// ---------------- kernel 2: top-4096 (32-bit search + tie index search) --------------
__device__ __forceinline__ ull shfl_xor_u64(ull x, int m) {
    unsigned lo = __shfl_xor_sync(0xFFFFFFFFu, (unsigned)x, m);
    unsigned hi = __shfl_xor_sync(0xFFFFFFFFu, (unsigned)(x >> 32), m);
    return ((ull)hi << 32) | lo;
}

#define NIT_U   16   // 2-bit steps over 32-bit u
#define NIT_I   15   // 1-bit steps over 15-bit index
// counter layout: [0..44] u-search iters 0..14 (3 each), [45..48] last iter (4),
// [49..63] index search
#define CNT_TOTAL 64

__global__ void __launch_bounds__(1024) k_select(const float* __restrict__ pred) {
    int b = blockIdx.x;
    int tid = threadIdx.x;
    int lane = tid & 31;
    const unsigned* u = g_u + b * NPRED;
    __shared__ ull keys[TOPK];
    __shared__ int cnts[CNT_TOTAL];
    __shared__ int scnt, svalid;

    // zero per-batch side state
    if (tid < NC) g_clsCnt[b * NC + tid] = 0;
    if (tid == 0) { g_ecnt[b] = 0; scnt = 0; svalid = 0; }
    if (tid < CNT_TOTAL) cnts[tid] = 0;

    // ---- load all keys into registers (full MLP, one pass over memory) ----
    unsigned uv[NITEMS];
    #pragma unroll
    for (int k = 0; k < NITEMS; ++k) {
        int i = k * 1024 + tid;
        uv[k] = (i < NPRED) ? u[i] : 0u;   // fake items get u=0 (never counted/selected)
    }
    __syncthreads();

    // ---- 2-bit-per-step search for u* = u-word of the 4096th-largest key ----
    unsigned U = 0u;           // identical in every thread
    #pragma unroll
    for (int it = 0; it < NIT_U - 1; ++it) {
        int s = 30 - 2 * it;
        unsigned c1t = U + (1u << s);
        int c1 = 0, c2 = 0, c3 = 0;
        #pragma unroll
        for (int k = 0; k < NITEMS; ++k) {
            unsigned k0 = uv[k];
            if (k0 >= c1t) {
                unsigned w = (k0 - U) >> s;
                c1++;
                if (w >= 2) c2++;
                if (w >= 3) c3++;
            }
        }
        c1 = __reduce_add_sync(0xFFFFFFFFu, c1);
        c2 = __reduce_add_sync(0xFFFFFFFFu, c2);
        c3 = __reduce_add_sync(0xFFFFFFFFu, c3);
        if (lane == 0) {
            atomicAdd(&cnts[it * 3 + 0], c1);
            atomicAdd(&cnts[it * 3 + 1], c2);
            atomicAdd(&cnts[it * 3 + 2], c3);
        }
        __syncthreads();
        int t1 = cnts[it * 3 + 0], t2 = cnts[it * 3 + 1], t3 = cnts[it * 3 + 2];
        unsigned v = (t3 >= TOPK) ? 3u : (t2 >= TOPK) ? 2u : (t1 >= TOPK) ? 1u : 0u;
        U |= v << s;           // every thread computes the same update: no 2nd sync
    }
    // last iteration (s=0) also counts w>=4 so C_gt comes for free
    int C_gt;
    {
        unsigned c1t = U + 1u;
        int c1 = 0, c2 = 0, c3 = 0, c4 = 0;
        #pragma unroll
        for (int k = 0; k < NITEMS; ++k) {
            unsigned k0 = uv[k];
            if (k0 >= c1t) {
                unsigned w = k0 - U;
                c1++;
                if (w >= 2) c2++;
                if (w >= 3) c3++;
                if (w >= 4) c4++;
            }
        }
        c1 = __reduce_add_sync(0xFFFFFFFFu, c1);
        c2 = __reduce_add_sync(0xFFFFFFFFu, c2);
        c3 = __reduce_add_sync(0xFFFFFFFFu, c3);
        c4 = __reduce_add_sync(0xFFFFFFFFu, c4);
        if (lane == 0) {
            atomicAdd(&cnts[45], c1);
            atomicAdd(&cnts[46], c2);
            atomicAdd(&cnts[47], c3);
            atomicAdd(&cnts[48], c4);
        }
        __syncthreads();
        int t1 = cnts[45], t2 = cnts[46], t3 = cnts[47], t4 = cnts[48];
        unsigned v = (t3 >= TOPK) ? 3u : (t2 >= TOPK) ? 2u : (t1 >= TOPK) ? 1u : 0u;
        U |= v;
        C_gt = (v == 0) ? t1 : (v == 1) ? t2 : (v == 2) ? t3 : t4;  // count(u > U)
    }
    unsigned ustar = U;
    int need = TOPK - C_gt;   // >= 1

    // ---- 15-bit search: M = largest x with #{u==u* && i<x} < need ----
    int M = 0;
    #pragma unroll
    for (int it = 0; it < NIT_I; ++it) {
        int bit = 14 - it;
        int cand = M | (1 << bit);
        int c = 0;
        #pragma unroll
        for (int k = 0; k < NITEMS; ++k) {
            int i = k * 1024 + tid;
            if (uv[k] == ustar && i < cand && i < NPRED) c++;
        }
        c = __reduce_add_sync(0xFFFFFFFFu, c);
        if (lane == 0) atomicAdd(&cnts[49 + it], c);
        __syncthreads();
        if (cnts[49 + it] < need) M = cand;   // same decision in every thread
    }
    // selection predicate: (u > u*) || (u == u* && i <= M)  -> exactly TOPK items

    // ---- gather exactly-4096 keys (warp-aggregated positions) ----
    #pragma unroll
    for (int k = 0; k < NITEMS; ++k) {
        int i = k * 1024 + tid;
        unsigned k0 = uv[k];
        bool m = (i < NPRED) && (k0 > ustar || (k0 == ustar && i <= M));
        unsigned act = __ballot_sync(0xFFFFFFFFu, m);
        if (m) {
            int leader = __ffs(act) - 1;
            int rank = __popc(act & ((1u << lane) - 1u));
            int base;
            if (lane == leader) base = atomicAdd(&scnt, __popc(act));
            base = __shfl_sync(act, base, leader);
            int pos = base + rank;
            if (pos < TOPK) keys[pos] = ((ull)k0 << 32) | (unsigned)(~i);
        }
    }
    __syncthreads();

    // ---- hybrid bitonic sort, descending: 4 elems/thread (blocked) ----
    ull v[4];
    #pragma unroll
    for (int e = 0; e < 4; ++e) v[e] = keys[tid * 4 + e];

    for (int k = 2; k <= TOPK; k <<= 1) {
        for (int j = k >> 1; j >= 1; j >>= 1) {
            if (j >= 128) {
                #pragma unroll
                for (int e = 0; e < 4; ++e) keys[tid * 4 + e] = v[e];
                __syncthreads();
                #pragma unroll
                for (int e = 0; e < 4; ++e) {
                    int idx = tid * 4 + e;
                    ull pv = keys[idx ^ j];
                    bool d = ((idx & k) == 0);
                    bool lower = ((idx & j) == 0);
                    bool keepmax = (d == lower);
                    ull mx = (v[e] > pv) ? v[e] : pv;
                    ull mn = (v[e] > pv) ? pv : v[e];
                    v[e] = keepmax ? mx : mn;
                }
                __syncthreads();
            } else if (j >= 4) {
                int dl = j >> 2;
                #pragma unroll
                for (int e = 0; e < 4; ++e) {
                    ull pv = shfl_xor_u64(v[e], dl);
                    int idx = tid * 4 + e;
                    bool d = ((idx & k) == 0);
                    bool lower = ((tid & dl) == 0);
                    bool keepmax = (d == lower);
                    ull mx = (v[e] > pv) ? v[e] : pv;
                    ull mn = (v[e] > pv) ? pv : v[e];
                    v[e] = keepmax ? mx : mn;
                }
            } else {
                #pragma unroll
                for (int e = 0; e < 4; ++e) {
                    if ((e & j) == 0) {
                        int idx = tid * 4 + e;
                        bool d = ((idx & k) == 0);
                        ull a = v[e], c2 = v[e + j];
                        if (d ? (a < c2) : (a > c2)) { v[e] = c2; v[e + j] = a; }
                    }
                }
            }
        }
    }

    // ---- emit + fused gather of boxes / classes / areas + class bucketing ----
    int lv = 0;
    #pragma unroll
    for (int e = 0; e < 4; ++e) {
        int rank = tid * 4 + e;
        ull key = v[e];
        int i = (int)(~(unsigned)(key & 0xFFFFFFFFull));
        int gi = b * TOPK + rank;
        float s = g_s[b * NPRED + i];
        g_selScore[gi] = s;
        lv += (s > 0.0f);
        int ci = g_cls[b * NPRED + i];
        g_selCls[gi] = ci;
        int slot = atomicAdd(&g_clsCnt[b * NC + ci], 1);
        g_clsList[(b * NC + ci) * TOPK + slot] = rank;
        const float* p = pred + ((size_t)b * NPRED + i) * STRIDE;
        float xc = p[0], yc = p[1], w = p[2], h = p[3];
        float hw = __fmul_rn(w, 0.5f), hh = __fmul_rn(h, 0.5f);
        float x1 = __fsub_rn(xc, hw), y1 = __fsub_rn(yc, hh);
        float x2 = __fadd_rn(xc, hw), y2 = __fadd_rn(yc, hh);
        float off = __fmul_rn((float)ci, MAX_WH);
        float ox1 = __fadd_rn(x1, off), oy1 = __fadd_rn(y1, off);
        float ox2 = __fadd_rn(x2, off), oy2 = __fadd_rn(y2, off);
        ((float4*)g_box)[gi] = make_float4(x1, y1, x2, y2);
        ((float4*)g_ob)[gi]  = make_float4(ox1, oy1, ox2, oy2);
        g_area[gi] = __fmul_rn(__fsub_rn(ox2, ox1), __fsub_rn(oy2, oy1));
    }
    lv = __reduce_add_sync(0xFFFFFFFFu, lv);
    if (lane == 0) atomicAdd(&svalid, lv);
    __syncthreads();
    if (tid == 0) g_nvalid[b] = svalid;
}

// ------------- kernel 3: per-class pairwise IoU -> suppression pair list -------------
__device__ __forceinline__ bool iou_exceeds(float ax1, float ay1, float ax2, float ay2,
                                            float aA,
                                            float bx1, float by1, float bx2, float by2,
                                            float aB) {
    float ltx = fmaxf(ax1, bx1);
    float lty = fmaxf(ay1, by1);
    float rbx = fminf(ax2, bx2);
    float rby = fminf(ay2, by2);
    float wv = fmaxf(__fsub_rn(rbx, ltx), 0.0f);
    float hv = fmaxf(__fsub_rn(rby, lty), 0.0f);
    float inter = __fmul_rn(wv, hv);
    if (inter <= 0.0f) return false;
    float denom = __fadd_rn(__fsub_rn(__fadd_rn(aA, aB), inter), 1e-7f);
    return __fdiv_rn(inter, denom) > IOU_THRES;
}

__global__ void __launch_bounds__(256) k_mask() {
    int c = blockIdx.x;     // class
    int b = blockIdx.y;     // batch
    int tid = threadIdx.x;
    int n = g_clsCnt[b * NC + c];
    if (n < 2) return;
    const int* gl = g_clsList + (b * NC + c) * TOPK;
    __shared__ float sx1[MCACHE], sy1[MCACHE], sx2[MCACHE], sy2[MCACHE], sar[MCACHE];
    __shared__ int   srk[MCACHE];
    bool cached = (n <= MCACHE);
    if (cached) {
        for (int s = tid; s < n; s += 256) {
            int r = gl[s];
            float4 B = ((const float4*)g_ob)[b * TOPK + r];
            sx1[s] = B.x; sy1[s] = B.y; sx2[s] = B.z; sy2[s] = B.w;
            sar[s] = g_area[b * TOPK + r];
            srk[s] = r;
        }
        __syncthreads();
    }
    long long total = (long long)n * (n - 1) / 2;
    for (long long p = tid; p < total; p += 256) {
        // map p -> (a,bq) in upper triangle, row-major
        float fn = (float)n;
        float pf = (float)p;
        int a = (int)(fn - 0.5f - sqrtf(fmaxf((fn - 0.5f) * (fn - 0.5f) - 2.0f * pf, 0.0f)));
        if (a < 0) a = 0; if (a > n - 2) a = n - 2;
        while ((long long)(a + 1) * n - (long long)(a + 1) * (a + 2) / 2 <= p) a++;
        while ((long long)a * n - (long long)a * (a + 1) / 2 > p) a--;
        long long fa = (long long)a * n - (long long)a * (a + 1) / 2;
        int bq = (int)(p - fa) + a + 1;
        bool hit; int r1, r2;
        if (cached) {
            r1 = srk[a]; r2 = srk[bq];
            hit = iou_exceeds(sx1[a], sy1[a], sx2[a], sy2[a], sar[a],
                              sx1[bq], sy1[bq], sx2[bq], sy2[bq], sar[bq]);
        } else {
            r1 = gl[a]; r2 = gl[bq];
            int gi = b * TOPK + r1, gj = b * TOPK + r2;
            float4 A = ((const float4*)g_ob)[gi];
            float4 B = ((const float4*)g_ob)[gj];
            hit = iou_exceeds(A.x, A.y, A.z, A.w, g_area[gi],
                              B.x, B.y, B.z, B.w, g_area[gj]);
        }
        if (hit) {
            int i = min(r1, r2), j = max(r1, r2);
            int e = atomicAdd(&g_ecnt[b], 1);
            if (e < ECAP) g_epair[b * ECAP + e] = ((unsigned)i << 12) | (unsigned)j;
        }
    }
}

// ------- kernel 4: greedy suppression via Jacobi fixpoint + fused output -------------
__global__ void __launch_bounds__(256) k_suppress(float* __restrict__ out) {
    int b = blockIdx.x;
    int tid = threadIdx.x;   // 256
    __shared__ unsigned sedge[ECAP];    // 32KB
    __shared__ ull remA[NWORDS], remB[NWORDS];
    __shared__ ull keepw[NWORDS];
    __shared__ int prefix[NWORDS];
    __shared__ int schanged;
    int nv = g_nvalid[b];
    int cnt = g_ecnt[b];
    if (tid < NWORDS) remA[tid] = 0ULL;

    if (cnt <= ECAP) {
        // ---- fast path: Jacobi fixpoint over the edge list (order-independent) ----
        // greedy NMS = unique fixpoint of alive(j) = valid(j) && !exists edge(i,j) alive(i)
        // (edges have i<j => well-founded; Jacobi iteration converges in depth+1 rounds)
        for (int e = tid; e < cnt; e += 256) sedge[e] = g_epair[b * ECAP + e];
        __syncthreads();
        for (int round = 0; round <= cnt; ++round) {
            if (tid < NWORDS) remB[tid] = 0ULL;
            if (tid == 0) schanged = 0;
            __syncthreads();
            for (int e = tid; e < cnt; e += 256) {
                unsigned k = sedge[e];
                int i = (int)(k >> 12);
                if (i < nv && !((remA[i >> 6] >> (i & 63)) & 1ULL)) {
                    int j = (int)(k & 4095u);
                    atomicOr(&remB[j >> 6], 1ULL << (j & 63));
                }
            }
            __syncthreads();
            if (tid < NWORDS && remB[tid] != remA[tid]) schanged = 1;  // benign race
            __syncthreads();
            if (!schanged) break;
            if (tid < NWORDS) remA[tid] = remB[tid];
            __syncthreads();
        }
    } else {
        // ---- fallback (never expected): exact serial greedy from class lists ----
        if (tid == 0) {
            for (int i = 0; i < nv; ++i) {
                if ((remA[i >> 6] >> (i & 63)) & 1ULL) continue;
                int c = g_selCls[b * TOPK + i];
                int n = g_clsCnt[b * NC + c];
                const int* gl = g_clsList + (b * NC + c) * TOPK;
                float4 A = ((const float4*)g_ob)[b * TOPK + i];
                float aA = g_area[b * TOPK + i];
                for (int s = 0; s < n; ++s) {
                    int j = gl[s];
                    if (j <= i) continue;
                    if ((remA[j >> 6] >> (j & 63)) & 1ULL) continue;
                    float4 B = ((const float4*)g_ob)[b * TOPK + j];
                    if (iou_exceeds(A.x, A.y, A.z, A.w, aA,
                                    B.x, B.y, B.z, B.w, g_area[b * TOPK + j]))
                        remA[j >> 6] |= (1ULL << (j & 63));
                }
            }
        }
        __syncthreads();
    }

    if (tid < NWORDS) {
        int lim = nv - tid * 64; if (lim > 64) lim = 64; if (lim < 0) lim = 0;
        ull valid = (lim >= 64) ? ~0ULL : ((lim <= 0) ? 0ULL : ((1ULL << lim) - 1ULL));
        keepw[tid] = valid & ~remA[tid];
    }
    __syncthreads();

    // ---- fused output compaction ----
    if (tid == 0) {
        int s = 0;
        for (int w = 0; w < NWORDS; ++w) { prefix[w] = s; s += __popcll(keepw[w]); }
    }
    float* o = out + (size_t)b * MAXDET * 6;
    for (int z = tid; z < MAXDET * 6; z += 256) o[z] = 0.0f;
    __syncthreads();
    for (int i = tid; i < TOPK; i += 256) {
        int w = i >> 6, bt = i & 63;
        if ((keepw[w] >> bt) & 1ULL) {
            int rank = prefix[w] + __popcll(keepw[w] & ((1ULL << bt) - 1ULL));
            if (rank < MAXDET) {
                int gi = b * TOPK + i;
                float* r = o + rank * 6;
                float4 bx = ((const float4*)g_box)[gi];
                r[0] = bx.x; r[1] = bx.y; r[2] = bx.z; r[3] = bx.w;
                r[4] = g_selScore[gi];
                r[5] = (float)g_selCls[gi];
            }
        }
    }
}

// ---------------- launch ---------------------------------------------------------------
extern "C" void kernel_launch(void* const* d_in, const int* in_sizes, int n_in,
                              void* d_out, int out_size) {
    const float* pred = (const float*)d_in[0];
    float* out = (float*)d_out;

    // 1) conf / argmax / order key : one warp per row
    {
        int rows = BATCH * NPRED;
        int threads = 256;
        int blocks = (rows * 32 + threads - 1) / threads;
        k_prep<<<blocks, threads>>>(pred);
    }
    // 2) exact top-4096 per batch + sort + fused gather + class bucketing
    k_select<<<BATCH, 1024>>>(pred);
    // 3) per-class pairwise IoU -> suppression pairs (shared box cache)
    {
        dim3 g(NC, BATCH);
        k_mask<<<g, 256>>>();
    }
    // 4) greedy suppression (fixpoint) + fused output
    k_suppress<<<BATCH, 256>>>(out);
}